// round 8
// baseline (speedup 1.0000x reference)
#include <cuda_runtime.h>
#include <cuda_bf16.h>

#define DD 96
#define NSEG 50
#define NT 301
#define BATCH 256
#define OUTW 4656          // 96 + 96*95/2
#define TILES_PB 8
#define GRID (BATCH * NSEG / TILES_PB)   // 1600

// ---- Youla decomposition of the 6x6 antisymmetric tridiagonal form ----
#define S1d 0.4338837391175581204757683328483
#define S2d 0.7818314824680298087084445266741
#define S3d 0.9749279121818236070181316829939
#define C1d 0.9009688679024191262361023195074
#define C2d 0.6234898018587335305250048840042
#define C3d 0.2225209339563144042889025644968
// A[i,j] = sum_k P_k[i] Q_k[j] - Q_k[i] P_k[j]
__device__ __constant__ float PA[3][3] = {
    { (float)(-(C1d/1.75)*S2d), (float)( (C1d/1.75)*S3d), (float)(-(C1d/1.75)*S1d) },
    { (float)(-(C2d/1.75)*S3d), (float)(-(C2d/1.75)*S1d), (float)( (C2d/1.75)*S2d) },
    { (float)(-(C3d/1.75)*S1d), (float)(-(C3d/1.75)*S2d), (float)(-(C3d/1.75)*S3d) },
};
__device__ __constant__ float QB[3][3] = {
    { (float)( S1d), (float)(-S3d), (float)( S2d) },
    { (float)( S2d), (float)(-S1d), (float)(-S3d) },
    { (float)( S3d), (float)( S2d), (float)( S1d) },
};

typedef unsigned long long u64;

__device__ __forceinline__ u64 fma2(u64 a, u64 b, u64 c) {
    u64 d; asm("fma.rn.f32x2 %0, %1, %2, %3;" : "=l"(d) : "l"(a), "l"(b), "l"(c)); return d;
}
__device__ __forceinline__ u64 mul2(u64 a, u64 b) {
    u64 d; asm("mul.rn.f32x2 %0, %1, %2;" : "=l"(d) : "l"(a), "l"(b)); return d;
}
__device__ __forceinline__ void unpack2(u64 v, float& lo, float& hi) {
    asm("mov.b64 {%0, %1}, %2;" : "=f"(lo), "=f"(hi) : "l"(v));
}

// double-buffered staging:
//  j-side scalar arrays (LDS.64 of 2 consecutive j):        Qsc, NPsc
//  row-side pre-duplicated {v,v} (broadcast LDS.64, hoisted
//  per GROUP into registers, reused across the jt tiles):   Pdup, Qdup
struct SBuf {
    float  Qsc[3][DD];
    float  NPsc[3][DD];
    float2 Pdup[3][DD];
    float2 Qdup[3][DD];
};

// One 8-row group (this half-warp: rows i0..i0+3, i0 = 8g + 4*half) over
// j-tiles jt = JTF..2. jt == JTF is the boundary tile (masked).
// Row classes by r = i mod 4: r=0,1 -> odd triangular base (2x STG.32);
// r=2,3 -> even base (STG.64 straight from the packed accumulator).
template<int JTF>
__device__ __forceinline__ void do_group(int g, int half, int jl,
                                         const SBuf* __restrict__ sb,
                                         float* __restrict__ o)
{
    const int i0 = 8 * g + 4 * half;

    // row-side packed operands: ONE broadcast LDS.64 each, live across all tiles
    u64 Pd[3][4], Qd[3][4];
    #pragma unroll
    for (int k = 0; k < 3; k++)
        #pragma unroll
        for (int r = 0; r < 4; r++) {
            Pd[k][r] = *(const u64*)&sb->Pdup[k][i0 + r];
            Qd[k][r] = *(const u64*)&sb->Qdup[k][i0 + r];
        }

    float* rb[4];
    #pragma unroll
    for (int r = 0; r < 4; r++) {
        const int i = i0 + r;
        rb[r] = o + DD + i * 95 - ((i * (i - 1)) >> 1) - i - 1 + 2 * jl;
    }

    #pragma unroll
    for (int jt = JTF; jt < 3; jt++) {
        u64 acc[4];
        #pragma unroll
        for (int k = 0; k < 3; k++) {
            const u64 qp  = *(const u64*)&sb->Qsc[k][32 * jt + 2 * jl];
            const u64 npp = *(const u64*)&sb->NPsc[k][32 * jt + 2 * jl];
            #pragma unroll
            for (int r = 0; r < 4; r++) {
                if (k == 0) acc[r] = mul2(Pd[0][r], qp);
                else        acc[r] = fma2(Pd[k][r], qp, acc[r]);
                acc[r] = fma2(Qd[k][r], npp, acc[r]);
            }
        }

        const int off = 32 * jt;
        if (jt == JTF) {
            const int j0 = 32 * JTF + 2 * jl;
            #pragma unroll
            for (int r = 0; r < 4; r++) {
                const int i = i0 + r;
                float lo, hi; unpack2(acc[r], lo, hi);
                if (r < 2) {
                    if (j0     > i) rb[r][off]     = lo;
                    if (j0 + 1 > i) rb[r][off + 1] = hi;
                } else {
                    if (j0 > i)       *(u64*)&rb[r][off] = acc[r];
                    else if (j0 == i) rb[r][off + 1] = hi;
                }
            }
        } else {
            #pragma unroll
            for (int r = 0; r < 4; r++) {
                if (r < 2) {
                    float lo, hi; unpack2(acc[r], lo, hi);
                    rb[r][off]     = lo;
                    rb[r][off + 1] = hi;
                } else {
                    *(u64*)&rb[r][off] = acc[r];
                }
            }
        }
    }
}

__global__ __launch_bounds__(256)
void logsig_kernel(const float* __restrict__ inp, float* __restrict__ out)
{
    __shared__ __align__(16) SBuf sb[2];

    const int tid  = threadIdx.x;
    const int warp = tid >> 5;
    const int lane = tid & 31;
    const int half = lane >> 4;
    const int jl   = lane & 15;

    const int bs0 = blockIdx.x * TILES_PB;

    // prefetch tile 0 inputs
    float pf[7];
    if (tid < DD) {
        const int b = bs0 / NSEG, s = bs0 - b * NSEG;
        const float* __restrict__ p = inp + ((size_t)b * NT + 6 * s) * DD + tid;
        #pragma unroll
        for (int t = 0; t < 7; t++) pf[t] = p[t * DD];
    }

    int buf = 0;
    for (int it = 0; it < TILES_PB; it++) {
        const int bs = bs0 + it;
        float* __restrict__ o = out + (size_t)bs * OUTW;

        // stage P/Q from prefetched registers
        if (tid < DD) {
            const float p0 = pf[0];
            const float y1 = pf[1] - p0, y2 = pf[2] - p0, y3 = pf[3] - p0;
            const float y4 = pf[4] - p0, y5 = pf[5] - p0, y6 = pf[6] - p0;
            o[tid] = y6;  // level-1 term
            #pragma unroll
            for (int k = 0; k < 3; k++) {
                float Pk = fmaf(PA[k][0], y2, fmaf(PA[k][1], y4, PA[k][2] * y6));
                float Qk = fmaf(QB[k][0], y1, fmaf(QB[k][1], y3, QB[k][2] * y5));
                sb[buf].Qsc[k][tid]  = Qk;
                sb[buf].NPsc[k][tid] = -Pk;
                sb[buf].Pdup[k][tid] = make_float2(Pk, Pk);
                sb[buf].Qdup[k][tid] = make_float2(Qk, Qk);
            }
        }
        __syncthreads();

        // prefetch next tile (latency hidden behind compute)
        if (it + 1 < TILES_PB && tid < DD) {
            const int bs2 = bs + 1;
            const int b2 = bs2 / NSEG, s2 = bs2 - b2 * NSEG;
            const float* __restrict__ p2 = inp + ((size_t)b2 * NT + 6 * s2) * DD + tid;
            #pragma unroll
            for (int t = 0; t < 7; t++) pf[t] = p2[t * DD];
        }

        // compute + store: 12 groups of 8 rows, 24 warp-tiles, 3 per warp
        const SBuf* sp = &sb[buf];
        if (warp < 4) {
            do_group<0>(warp, half, jl, sp, o);          // groups 0-3: jt 0,1,2
        } else {
            do_group<1>(warp, half, jl, sp, o);          // groups 4-7: jt 1,2
            do_group<2>(warp + 4, half, jl, sp, o);      // groups 8-11: jt 2
        }

        buf ^= 1;
        // one barrier per iteration suffices with double buffering:
        // compute(t) reads buf; the next write of buf is stage(t+2), which is
        // separated from compute(t) by the iter-(t+1) barrier.
    }
}

extern "C" void kernel_launch(void* const* d_in, const int* in_sizes, int n_in,
                              void* d_out, int out_size)
{
    const float* inp = (const float*)d_in[0];
    float* out = (float*)d_out;
    logsig_kernel<<<GRID, 256>>>(inp, out);
}

// round 9
// speedup vs baseline: 1.1326x; 1.1326x over previous
#include <cuda_runtime.h>
#include <cuda_bf16.h>

#define DD 96
#define NSEG 50
#define NT 301
#define BATCH 256
#define OUTW 4656          // 96 + 96*95/2
#define TILES_PB 8
#define PAIRS (TILES_PB / 2)
#define GRID (BATCH * NSEG / TILES_PB)   // 1600

// ---- Youla decomposition of the 6x6 antisymmetric tridiagonal form ----
#define S1d 0.4338837391175581204757683328483
#define S2d 0.7818314824680298087084445266741
#define S3d 0.9749279121818236070181316829939
#define C1d 0.9009688679024191262361023195074
#define C2d 0.6234898018587335305250048840042
#define C3d 0.2225209339563144042889025644968
// A[i,j] = sum_k P_k[i] Q_k[j] - Q_k[i] P_k[j]
__device__ __constant__ float PA[3][3] = {
    { (float)(-(C1d/1.75)*S2d), (float)( (C1d/1.75)*S3d), (float)(-(C1d/1.75)*S1d) },
    { (float)(-(C2d/1.75)*S3d), (float)(-(C2d/1.75)*S1d), (float)( (C2d/1.75)*S2d) },
    { (float)(-(C3d/1.75)*S1d), (float)(-(C3d/1.75)*S2d), (float)(-(C3d/1.75)*S3d) },
};
__device__ __constant__ float QB[3][3] = {
    { (float)( S1d), (float)(-S3d), (float)( S2d) },
    { (float)( S2d), (float)(-S1d), (float)(-S3d) },
    { (float)( S3d), (float)( S2d), (float)( S1d) },
};

typedef unsigned long long u64;

__device__ __forceinline__ u64 fma2(u64 a, u64 b, u64 c) {
    u64 d; asm("fma.rn.f32x2 %0, %1, %2, %3;" : "=l"(d) : "l"(a), "l"(b), "l"(c)); return d;
}
__device__ __forceinline__ u64 mul2(u64 a, u64 b) {
    u64 d; asm("mul.rn.f32x2 %0, %1, %2;" : "=l"(d) : "l"(a), "l"(b)); return d;
}
__device__ __forceinline__ void unpack2(u64 v, float& lo, float& hi) {
    asm("mov.b64 {%0, %1}, %2;" : "=f"(lo), "=f"(hi) : "l"(v));
}

// R4 layout: row-side contiguous scalars (LDS.64 pair loads), j-side
// pre-duplicated {v,v} (plain LDS.64, no per-tile pack MOVs)
struct SBuf {
    float  Ps[3][DD];
    float  Qs[3][DD];
    float2 Qdup[3][DD];
    float2 NPdup[3][DD];
};

// R4 body: warp handles i0 = 32*band + 4*warp for band = 0..2, j-tiles
// jt = band..2; boundary tile (jt == band) masked by lane > t4 + r.
__device__ __forceinline__ void compute_seg(int t4, int lane,
                                            const SBuf* __restrict__ sb,
                                            float* __restrict__ o)
{
    #pragma unroll
    for (int band = 0; band < 3; band++) {
        const int i0 = 32 * band + t4;

        u64 PPa[3], PPb[3], QQa[3], QQb[3];
        #pragma unroll
        for (int k = 0; k < 3; k++) {
            PPa[k] = *(const u64*)&sb->Ps[k][i0];
            PPb[k] = *(const u64*)&sb->Ps[k][i0 + 2];
            QQa[k] = *(const u64*)&sb->Qs[k][i0];
            QQb[k] = *(const u64*)&sb->Qs[k][i0 + 2];
        }

        float* rp[4];
        #pragma unroll
        for (int r = 0; r < 4; r++) {
            const int i = i0 + r;
            rp[r] = o + DD + i * 95 - ((i * (i - 1)) >> 1) - i - 1 + lane;
        }

        #pragma unroll
        for (int jt = band; jt < 3; jt++) {
            const int j = (jt << 5) + lane;

            u64 acc_a, acc_b;
            {
                const u64 qj  = *(const u64*)&sb->Qdup[0][j];
                const u64 npj = *(const u64*)&sb->NPdup[0][j];
                acc_a = mul2(PPa[0], qj);
                acc_b = mul2(PPb[0], qj);
                acc_a = fma2(QQa[0], npj, acc_a);
                acc_b = fma2(QQb[0], npj, acc_b);
            }
            #pragma unroll
            for (int k = 1; k < 3; k++) {
                const u64 qj  = *(const u64*)&sb->Qdup[k][j];
                const u64 npj = *(const u64*)&sb->NPdup[k][j];
                acc_a = fma2(PPa[k], qj, acc_a);
                acc_b = fma2(PPb[k], qj, acc_b);
                acc_a = fma2(QQa[k], npj, acc_a);
                acc_b = fma2(QQb[k], npj, acc_b);
            }

            float v0, v1, v2, v3;
            unpack2(acc_a, v0, v1);
            unpack2(acc_b, v2, v3);

            const int off = jt << 5;
            if (jt == band) {
                if (lane > t4)     rp[0][off] = v0;
                if (lane > t4 + 1) rp[1][off] = v1;
                if (lane > t4 + 2) rp[2][off] = v2;
                if (lane > t4 + 3) rp[3][off] = v3;
            } else {
                rp[0][off] = v0;
                rp[1][off] = v1;
                rp[2][off] = v2;
                rp[3][off] = v3;
            }
        }
    }
}

__global__ __launch_bounds__(256)
void logsig_kernel(const float* __restrict__ inp, float* __restrict__ out)
{
    __shared__ __align__(16) SBuf sb[2][2];   // [pair parity][segment in pair]

    const int tid  = threadIdx.x;
    const int warp = tid >> 5;
    const int lane = tid & 31;
    const int t4   = 4 * warp;

    const int bs0 = blockIdx.x * TILES_PB;

    // staging role: tid < 192 handles (seg = tid/96, d = tid%96)
    const int seg = tid / DD;          // 0,1 for stagers (tid < 192)
    const int d   = tid - seg * DD;

    // prefetch pair 0 (both segments)
    float pf[7];
    if (tid < 2 * DD) {
        const int bs = bs0 + seg;
        const int b = bs / NSEG, s = bs - b * NSEG;
        const float* __restrict__ p = inp + ((size_t)b * NT + 6 * s) * DD + d;
        #pragma unroll
        for (int t = 0; t < 7; t++) pf[t] = p[t * DD];
    }

    for (int pr = 0; pr < PAIRS; pr++) {
        const int bsA = bs0 + 2 * pr;
        float* __restrict__ oA = out + (size_t)bsA * OUTW;
        float* __restrict__ oB = oA + OUTW;

        // stage both segments of the pair (192 threads in parallel)
        if (tid < 2 * DD) {
            SBuf* sd = &sb[pr & 1][seg];
            float* os = seg ? oB : oA;
            const float p0 = pf[0];
            const float y1 = pf[1] - p0, y2 = pf[2] - p0, y3 = pf[3] - p0;
            const float y4 = pf[4] - p0, y5 = pf[5] - p0, y6 = pf[6] - p0;
            os[d] = y6;  // level-1 term
            #pragma unroll
            for (int k = 0; k < 3; k++) {
                float Pk = fmaf(PA[k][0], y2, fmaf(PA[k][1], y4, PA[k][2] * y6));
                float Qk = fmaf(QB[k][0], y1, fmaf(QB[k][1], y3, QB[k][2] * y5));
                sd->Ps[k][d]    = Pk;
                sd->Qs[k][d]    = Qk;
                sd->Qdup[k][d]  = make_float2(Qk, Qk);
                sd->NPdup[k][d] = make_float2(-Pk, -Pk);
            }
        }
        __syncthreads();

        // prefetch next pair (latency hidden behind this pair's compute)
        if (pr + 1 < PAIRS && tid < 2 * DD) {
            const int bs2 = bs0 + 2 * (pr + 1) + seg;
            const int b2 = bs2 / NSEG, s2 = bs2 - b2 * NSEG;
            const float* __restrict__ p2 = inp + ((size_t)b2 * NT + 6 * s2) * DD + d;
            #pragma unroll
            for (int t = 0; t < 7; t++) pf[t] = p2[t * DD];
        }

        // compute + store both segments (two independent store streams)
        compute_seg(t4, lane, &sb[pr & 1][0], oA);
        compute_seg(t4, lane, &sb[pr & 1][1], oB);

        // one barrier per pair suffices: compute(pr) reads buf (pr&1); the next
        // write of that buf is stage(pr+2), and barrier(pr+1) separates every
        // thread's compute(pr) from every thread's stage(pr+2).
    }
}

extern "C" void kernel_launch(void* const* d_in, const int* in_sizes, int n_in,
                              void* d_out, int out_size)
{
    const float* inp = (const float*)d_in[0];
    float* out = (float*)d_out;
    logsig_kernel<<<GRID, 256>>>(inp, out);
}

// round 10
// speedup vs baseline: 1.1843x; 1.0457x over previous
#include <cuda_runtime.h>
#include <cuda_bf16.h>

#define DD 96
#define NSEG 50
#define NT 301
#define BATCH 256
#define OUTW 4656          // 96 + 96*95/2
#define TILES_PB 8
#define PAIRS (TILES_PB / 2)
#define GRID (BATCH * NSEG / TILES_PB)   // 1600

// ---- Youla decomposition of the 6x6 antisymmetric tridiagonal form ----
#define S1d 0.4338837391175581204757683328483
#define S2d 0.7818314824680298087084445266741
#define S3d 0.9749279121818236070181316829939
#define C1d 0.9009688679024191262361023195074
#define C2d 0.6234898018587335305250048840042
#define C3d 0.2225209339563144042889025644968
// A[i,j] = sum_k P_k[i] Q_k[j] - Q_k[i] P_k[j]
__device__ __constant__ float PA[3][3] = {
    { (float)(-(C1d/1.75)*S2d), (float)( (C1d/1.75)*S3d), (float)(-(C1d/1.75)*S1d) },
    { (float)(-(C2d/1.75)*S3d), (float)(-(C2d/1.75)*S1d), (float)( (C2d/1.75)*S2d) },
    { (float)(-(C3d/1.75)*S1d), (float)(-(C3d/1.75)*S2d), (float)(-(C3d/1.75)*S3d) },
};
__device__ __constant__ float QB[3][3] = {
    { (float)( S1d), (float)(-S3d), (float)( S2d) },
    { (float)( S2d), (float)(-S1d), (float)(-S3d) },
    { (float)( S3d), (float)( S2d), (float)( S1d) },
};

typedef unsigned long long u64;

__device__ __forceinline__ u64 pack2f(float lo, float hi) {
    u64 r; asm("mov.b64 %0, {%1, %2};" : "=l"(r) : "f"(lo), "f"(hi)); return r;
}
__device__ __forceinline__ u64 fma2(u64 a, u64 b, u64 c) {
    u64 d; asm("fma.rn.f32x2 %0, %1, %2, %3;" : "=l"(d) : "l"(a), "l"(b), "l"(c)); return d;
}
__device__ __forceinline__ u64 mul2(u64 a, u64 b) {
    u64 d; asm("mul.rn.f32x2 %0, %1, %2;" : "=l"(d) : "l"(a), "l"(b)); return d;
}
__device__ __forceinline__ float hsum2(u64 v) {   // lo + hi (halves are a reg pair; no real movs)
    float lo, hi;
    asm("mov.b64 {%0, %1}, %2;" : "=f"(lo), "=f"(hi) : "l"(v));
    return lo + hi;
}

// Complex-packed staging:
//  rowPQ[k][i] = {P_ki, -Q_ki}   (row side; LDS.128 fetches 2 rows at once, broadcast)
//  colPQ[k][j] = {Q_kj,  P_kj}   (j side; one LDS.64 per (k, tile))
// acc(i,j) = sum_k rowPQ[k][i] *2 colPQ[k][j]  -> halves sum to A[i,j].
struct SBuf {
    float2 rowPQ[3][DD];
    float2 colPQ[3][DD];
};

// Warp body (R4/R9 band structure): i0 = 32*band + 4*warp, jt = band..2;
// boundary tile jt==band masked by lane > t4 + r.
__device__ __forceinline__ void compute_seg(int t4, int lane,
                                            const SBuf* __restrict__ sb,
                                            float* __restrict__ o)
{
    #pragma unroll
    for (int band = 0; band < 3; band++) {
        const int i0 = 32 * band + t4;

        // row-side packed operands: 2 rows per broadcast LDS.128
        u64 rp[3][4];
        #pragma unroll
        for (int k = 0; k < 3; k++) {
            const float4 fa = *(const float4*)&sb->rowPQ[k][i0];       // rows i0, i0+1
            const float4 fb = *(const float4*)&sb->rowPQ[k][i0 + 2];   // rows i0+2, i0+3
            rp[k][0] = pack2f(fa.x, fa.y);
            rp[k][1] = pack2f(fa.z, fa.w);
            rp[k][2] = pack2f(fb.x, fb.y);
            rp[k][3] = pack2f(fb.z, fb.w);
        }

        float* rb[4];
        #pragma unroll
        for (int r = 0; r < 4; r++) {
            const int i = i0 + r;
            rb[r] = o + DD + i * 95 - ((i * (i - 1)) >> 1) - i - 1 + lane;
        }

        #pragma unroll
        for (int jt = band; jt < 3; jt++) {
            const int j = (jt << 5) + lane;

            const u64 c0 = *(const u64*)&sb->colPQ[0][j];
            const u64 c1 = *(const u64*)&sb->colPQ[1][j];
            const u64 c2 = *(const u64*)&sb->colPQ[2][j];

            u64 acc[4];
            #pragma unroll
            for (int r = 0; r < 4; r++) {
                acc[r] = mul2(rp[0][r], c0);
                acc[r] = fma2(rp[1][r], c1, acc[r]);
                acc[r] = fma2(rp[2][r], c2, acc[r]);
            }

            const int off = jt << 5;
            if (jt == band) {
                if (lane > t4)     rb[0][off] = hsum2(acc[0]);
                if (lane > t4 + 1) rb[1][off] = hsum2(acc[1]);
                if (lane > t4 + 2) rb[2][off] = hsum2(acc[2]);
                if (lane > t4 + 3) rb[3][off] = hsum2(acc[3]);
            } else {
                rb[0][off] = hsum2(acc[0]);
                rb[1][off] = hsum2(acc[1]);
                rb[2][off] = hsum2(acc[2]);
                rb[3][off] = hsum2(acc[3]);
            }
        }
    }
}

__global__ __launch_bounds__(256)
void logsig_kernel(const float* __restrict__ inp, float* __restrict__ out)
{
    __shared__ __align__(16) SBuf sb[2][2];   // [pair parity][segment in pair]

    const int tid  = threadIdx.x;
    const int warp = tid >> 5;
    const int lane = tid & 31;
    const int t4   = 4 * warp;

    const int bs0 = blockIdx.x * TILES_PB;

    // staging role: tid < 192 handles (seg = tid/96, d = tid%96)
    const int seg = tid / DD;
    const int d   = tid - seg * DD;

    // prefetch pair 0 (both segments)
    float pf[7];
    if (tid < 2 * DD) {
        const int bs = bs0 + seg;
        const int b = bs / NSEG, s = bs - b * NSEG;
        const float* __restrict__ p = inp + ((size_t)b * NT + 6 * s) * DD + d;
        #pragma unroll
        for (int t = 0; t < 7; t++) pf[t] = p[t * DD];
    }

    for (int pr = 0; pr < PAIRS; pr++) {
        const int bsA = bs0 + 2 * pr;
        float* __restrict__ oA = out + (size_t)bsA * OUTW;
        float* __restrict__ oB = oA + OUTW;

        // stage both segments of the pair (192 threads in parallel)
        if (tid < 2 * DD) {
            SBuf* sd = &sb[pr & 1][seg];
            float* os = seg ? oB : oA;
            const float p0 = pf[0];
            const float y1 = pf[1] - p0, y2 = pf[2] - p0, y3 = pf[3] - p0;
            const float y4 = pf[4] - p0, y5 = pf[5] - p0, y6 = pf[6] - p0;
            os[d] = y6;  // level-1 term
            #pragma unroll
            for (int k = 0; k < 3; k++) {
                float Pk = fmaf(PA[k][0], y2, fmaf(PA[k][1], y4, PA[k][2] * y6));
                float Qk = fmaf(QB[k][0], y1, fmaf(QB[k][1], y3, QB[k][2] * y5));
                sd->rowPQ[k][d] = make_float2(Pk, -Qk);
                sd->colPQ[k][d] = make_float2(Qk,  Pk);
            }
        }
        __syncthreads();

        // prefetch next pair (latency hidden behind this pair's compute)
        if (pr + 1 < PAIRS && tid < 2 * DD) {
            const int bs2 = bs0 + 2 * (pr + 1) + seg;
            const int b2 = bs2 / NSEG, s2 = bs2 - b2 * NSEG;
            const float* __restrict__ p2 = inp + ((size_t)b2 * NT + 6 * s2) * DD + d;
            #pragma unroll
            for (int t = 0; t < 7; t++) pf[t] = p2[t * DD];
        }

        // compute + store both segments (two independent store streams)
        compute_seg(t4, lane, &sb[pr & 1][0], oA);
        compute_seg(t4, lane, &sb[pr & 1][1], oB);

        // one barrier per pair suffices: compute(pr) reads buf (pr&1); the next
        // write of that buf is stage(pr+2), and barrier(pr+1) separates every
        // thread's compute(pr) from every thread's stage(pr+2).
    }
}

extern "C" void kernel_launch(void* const* d_in, const int* in_sizes, int n_in,
                              void* d_out, int out_size)
{
    const float* inp = (const float*)d_in[0];
    float* out = (float*)d_out;
    logsig_kernel<<<GRID, 256>>>(inp, out);
}